// round 1
// baseline (speedup 1.0000x reference)
#include <cuda_runtime.h>
#include <cstdint>
#include <cstddef>

// ---------------- problem constants ----------------
#define STEPS 100
#define BATCH 64
#define NSPK  (STEPS*BATCH*3*32*32)   // 19,660,800 poisson spikes
#define XSZ   (BATCH*3*32*32)         // 196,608
#define N1    (BATCH*32*14*14)        // 401,408 layer-1 neurons (per step)
#define N2    (BATCH*64*5*5)          // 102,400 layer-2 neurons (per step)
#define TB    (STEPS*BATCH)           // 6400

// ---------------- scratch (device globals; no cudaMalloc allowed) ----------
__device__ unsigned char g_spk0[NSPK];                    // poisson spikes, [t][b][c][h][w]
__device__ float         g_curin[(size_t)STEPS*N1];       // [t][b][oc][sp14x14]
__device__ unsigned char g_spkin[(size_t)STEPS*N1];
__device__ float         g_curh1[(size_t)STEPS*N2];       // [t][b][oc][sp5x5]
__device__ unsigned char g_spkh1[(size_t)STEPS*N2];
__device__ float         g_fc[STEPS*BATCH*10];
__device__ float         g_Wp1[3*36*32];                  // pooled conv1 weights [c][uv][oc]
__device__ float         g_Wp2[32*36*64];                 // pooled conv2 weights [c][uv][oc]

// ---------------- threefry2x32 (JAX-exact) ----------------
__device__ __forceinline__ uint2 threefry2x32(uint32_t k0, uint32_t k1,
                                              uint32_t x0, uint32_t x1) {
    uint32_t ks0 = k0, ks1 = k1, ks2 = k0 ^ k1 ^ 0x1BD11BDAu;
    x0 += ks0; x1 += ks1;
#define TFR(r) { x0 += x1; x1 = (x1 << (r)) | (x1 >> (32 - (r))); x1 ^= x0; }
    TFR(13) TFR(15) TFR(26) TFR(6)
    x0 += ks1; x1 += ks2 + 1u;
    TFR(17) TFR(29) TFR(16) TFR(24)
    x0 += ks2; x1 += ks0 + 2u;
    TFR(13) TFR(15) TFR(26) TFR(6)
    x0 += ks0; x1 += ks1 + 3u;
    TFR(17) TFR(29) TFR(16) TFR(24)
    x0 += ks1; x1 += ks2 + 4u;
    TFR(13) TFR(15) TFR(26) TFR(6)
    x0 += ks2; x1 += ks0 + 5u;
#undef TFR
    return make_uint2(x0, x1);
}

// ---------------- k0: fold avgpool(2x2,/4) into conv weights ----------------
// Wp[c][u][v][oc] = 0.25 * sum_{dh,dw in {0,1}, 0<=u-dh<5, 0<=v-dw<5} W[oc][c][u-dh][v-dw]
__global__ void k_fold(const float* __restrict__ Win, const float* __restrict__ Wh1) {
    int i = blockIdx.x * blockDim.x + threadIdx.x;
    if (i < 3*36*32) {
        int oc = i & 31; int r = i >> 5; int uv = r % 36; int c = r / 36;
        int u = uv / 6, v = uv % 6;
        float s = 0.f;
        #pragma unroll
        for (int dh = 0; dh < 2; dh++)
            #pragma unroll
            for (int dw = 0; dw < 2; dw++) {
                int kh = u - dh, kw = v - dw;
                if (kh >= 0 && kh < 5 && kw >= 0 && kw < 5)
                    s += Win[(oc*3 + c)*25 + kh*5 + kw];
            }
        g_Wp1[i] = 0.25f * s;
    }
    if (i < 32*36*64) {
        int oc = i & 63; int r = i >> 6; int uv = r % 36; int c = r / 36;
        int u = uv / 6, v = uv % 6;
        float s = 0.f;
        #pragma unroll
        for (int dh = 0; dh < 2; dh++)
            #pragma unroll
            for (int dw = 0; dw < 2; dw++) {
                int kh = u - dh, kw = v - dw;
                if (kh >= 0 && kh < 5 && kw >= 0 && kw < 5)
                    s += Wh1[(oc*32 + c)*25 + kh*5 + kw];
            }
        g_Wp2[i] = 0.25f * s;
    }
}

// ---------------- k1: poisson spike generation (JAX partitionable threefry) --
__global__ void k_spikes(const float* __restrict__ x) {
    int i = blockIdx.x * blockDim.x + threadIdx.x;
    if (i >= NSPK) return;
    uint2 r = threefry2x32(0u, 1u, 0u, (uint32_t)i);
    uint32_t bits = r.x ^ r.y;
    float u = __uint_as_float((bits >> 9) | 0x3f800000u) - 1.0f;
    int pos = i % XSZ;                     // [b][c][h][w] position
    g_spk0[i] = (u < x[pos] * 2.0f) ? 1 : 0;
}

// ---------------- k2: conv1(5x5) + avgpool fused via pooled 6x6 kernel ------
// one block per (t,b); thread = pooled spatial position, 32 oc accumulators
__global__ void k_conv1(void) {
    __shared__ float sIn[3*32*32];
    __shared__ __align__(16) float sW[3*36*32];
    int tb = blockIdx.x;
    const unsigned char* inp = g_spk0 + (size_t)tb * 3072;
    for (int i = threadIdx.x; i < 3072; i += blockDim.x) sIn[i] = (float)inp[i];
    for (int i = threadIdx.x; i < 3456; i += blockDim.x) sW[i] = g_Wp1[i];
    __syncthreads();

    int sp = threadIdx.x;
    if (sp >= 196) return;
    int ph = sp / 14, pw = sp % 14;
    float acc[32];
    #pragma unroll
    for (int j = 0; j < 32; j++) acc[j] = 0.f;

    int ibase = ph*64 + pw*2;              // (2ph)*32 + 2pw
    for (int c = 0; c < 3; c++) {
        const float* sI  = &sIn[c*1024 + ibase];
        const float* sWc = &sW[c*36*32];
        for (int u = 0; u < 6; u++) {
            #pragma unroll
            for (int v = 0; v < 6; v++) {
                float s = sI[u*32 + v];
                const float4* w4 = (const float4*)&sWc[(u*6 + v)*32];
                #pragma unroll
                for (int j = 0; j < 8; j++) {
                    float4 w = w4[j];
                    acc[4*j+0] += s * w.x;
                    acc[4*j+1] += s * w.y;
                    acc[4*j+2] += s * w.z;
                    acc[4*j+3] += s * w.w;
                }
            }
        }
    }
    size_t ob = (size_t)tb * (32*196);
    #pragma unroll 32
    for (int oc = 0; oc < 32; oc++) g_curin[ob + oc*196 + sp] = acc[oc];
}

// ---------------- k3: LIF scan layer 1 (mem[t]=cur[t]-spk[t-1]) ------------
__global__ void k_lif1(void) {
    int n = blockIdx.x * blockDim.x + threadIdx.x;
    if (n >= N1) return;
    float spk = 0.f;
    for (int t = 0; t < STEPS; t++) {
        float mem = g_curin[(size_t)t*N1 + n] - spk;
        spk = (mem > 1.0f) ? 1.0f : 0.0f;
        g_spkin[(size_t)t*N1 + n] = (unsigned char)(mem > 1.0f);
    }
}

// ---------------- k4: conv2 + pool, SPARSE over active input spikes --------
// block per (t,b). Deterministic per-channel active list; per-c weight slice
// staged in shared. Thread = (spatial pos, oc-octet): pure FADD gather.
__global__ void k_conv2(void) {
    __shared__ unsigned char sList[32*196];
    __shared__ int sCnt[32];
    __shared__ __align__(16) float sW[36*64];

    int tb  = blockIdx.x;
    int tid = threadIdx.x;
    const unsigned char* inp = g_spkin + (size_t)tb * 6272;

    // deterministic active-list build: one thread per input channel, fixed order
    if (tid < 32) {
        int c = tid, n = 0;
        const unsigned char* pc = inp + c*196;
        for (int ih = 0; ih < 14; ih++)
            for (int iw = 0; iw < 14; iw++)
                if (pc[ih*14 + iw]) sList[c*196 + (n++)] = (unsigned char)((ih << 4) | iw);
        sCnt[c] = n;
    }

    int active = (tid < 200);
    int sp = tid >> 3;            // pooled spatial 0..24 (for active threads)
    int og = tid & 7;             // oc octet: oc = og*8 .. og*8+7
    int ph = sp / 5, pw = sp % 5;
    int ph2 = 2*ph, pw2 = 2*pw;
    float acc[8];
    #pragma unroll
    for (int j = 0; j < 8; j++) acc[j] = 0.f;

    for (int c = 0; c < 32; c++) {
        for (int i = tid; i < 2304; i += 256) sW[i] = g_Wp2[c*2304 + i];
        __syncthreads();              // also orders sList build before first use
        if (active) {
            int n = sCnt[c];
            const unsigned char* lst = &sList[c*196];
            for (int j = 0; j < n; j++) {
                int p = lst[j];
                int u = (p >> 4) - ph2;
                int v = (p & 15) - pw2;
                if ((unsigned)u < 6u && (unsigned)v < 6u) {
                    const float* w = &sW[(u*6 + v)*64 + og*8];
                    float4 a = *(const float4*)w;
                    float4 b = *(const float4*)(w + 4);
                    acc[0] += a.x; acc[1] += a.y; acc[2] += a.z; acc[3] += a.w;
                    acc[4] += b.x; acc[5] += b.y; acc[6] += b.z; acc[7] += b.w;
                }
            }
        }
        __syncthreads();              // protect sW reload next iteration
    }

    if (active) {
        size_t ob = (size_t)tb * 1600;
        #pragma unroll
        for (int j = 0; j < 8; j++)
            g_curh1[ob + (og*8 + j)*25 + sp] = acc[j];
    }
}

// ---------------- k5: LIF scan layer 2 -------------------------------------
__global__ void k_lif2(void) {
    int n = blockIdx.x * blockDim.x + threadIdx.x;
    if (n >= N2) return;
    float spk = 0.f;
    for (int t = 0; t < STEPS; t++) {
        float mem = g_curh1[(size_t)t*N2 + n] - spk;
        spk = (mem > 1.0f) ? 1.0f : 0.0f;
        g_spkh1[(size_t)t*N2 + n] = (unsigned char)(mem > 1.0f);
    }
}

// ---------------- k6: FC [6400,1600] x [1600,10] ---------------------------
// block per (t,b), 10 warps (one per output), lane-strided reduction
__global__ void k_fc(const float* __restrict__ Wh2) {
    int tb = blockIdx.x;
    int o = threadIdx.x >> 5;
    int lane = threadIdx.x & 31;
    const unsigned char* s = g_spkh1 + (size_t)tb * 1600;
    const float* w = Wh2 + o*1600;
    float acc = 0.f;
    for (int f = lane; f < 1600; f += 32) acc += (float)s[f] * w[f];
    #pragma unroll
    for (int off = 16; off; off >>= 1) acc += __shfl_down_sync(0xffffffffu, acc, off);
    if (lane == 0) g_fc[tb*10 + o] = acc;
}

// ---------------- k7: output LIF scan + write spikes and mem ---------------
__global__ void k_lif3(float* __restrict__ out) {
    int i = blockIdx.x * blockDim.x + threadIdx.x;
    if (i >= BATCH*10) return;
    float spk = 0.f;
    for (int t = 0; t < STEPS; t++) {
        float mem = g_fc[t*640 + i] - spk;
        spk = (mem > 1.0f) ? 1.0f : 0.0f;
        out[t*640 + i] = spk;                    // out_spikes [100,64,10]
        out[STEPS*640 + t*640 + i] = mem;        // memh2      [100,64,10]
    }
}

// ---------------- launcher -------------------------------------------------
extern "C" void kernel_launch(void* const* d_in, const int* in_sizes, int n_in,
                              void* d_out, int out_size) {
    const float* x   = (const float*)d_in[0];   // [64,3,32,32]
    const float* Win = (const float*)d_in[1];   // [32,3,5,5]
    const float* Wh1 = (const float*)d_in[2];   // [64,32,5,5]
    const float* Wh2 = (const float*)d_in[3];   // [10,1600]
    float* out = (float*)d_out;

    k_fold  <<<288, 256>>>(Win, Wh1);
    k_spikes<<<(NSPK + 255)/256, 256>>>(x);
    k_conv1 <<<TB, 224>>>();
    k_lif1  <<<(N1 + 255)/256, 256>>>();
    k_conv2 <<<TB, 256>>>();
    k_lif2  <<<(N2 + 255)/256, 256>>>();
    k_fc    <<<TB, 320>>>(Wh2);
    k_lif3  <<<3, 256>>>(out);
}

// round 2
// speedup vs baseline: 1.0477x; 1.0477x over previous
#include <cuda_runtime.h>
#include <cstdint>
#include <cstddef>

// ---------------- problem constants ----------------
#define STEPS 100
#define BATCH 64
#define NSPK  (STEPS*BATCH*3*32*32)   // 19,660,800 poisson spikes
#define XSZ   (BATCH*3*32*32)         // 196,608
#define N1    (BATCH*32*14*14)        // 401,408 layer-1 neurons (per step)
#define N2    (BATCH*64*5*5)          // 102,400 layer-2 neurons (per step)
#define TB    (STEPS*BATCH)           // 6400

// ---------------- scratch (device globals; no cudaMalloc allowed) ----------
__device__ unsigned char g_spk0[NSPK];                    // poisson spikes, [t][b][c][h][w]
__device__ float         g_curin[(size_t)STEPS*N1];       // [t][b][oc][sp14x14]
__device__ unsigned char g_spkin[(size_t)STEPS*N1];
__device__ float         g_curh1[(size_t)STEPS*N2];       // [t][b][oc][sp5x5]
__device__ unsigned char g_spkh1[(size_t)STEPS*N2];
__device__ float         g_fc[STEPS*BATCH*10];
__device__ float         g_Wp1[3*36*32];                  // pooled conv1 weights [c][uv][oc]
__device__ float         g_Wp2[32*36*64];                 // pooled conv2 weights [c][uv][oc]

// ---------------- threefry2x32 (JAX-exact) ----------------
__device__ __forceinline__ uint2 threefry2x32(uint32_t k0, uint32_t k1,
                                              uint32_t x0, uint32_t x1) {
    uint32_t ks0 = k0, ks1 = k1, ks2 = k0 ^ k1 ^ 0x1BD11BDAu;
    x0 += ks0; x1 += ks1;
#define TFR(r) { x0 += x1; x1 = (x1 << (r)) | (x1 >> (32 - (r))); x1 ^= x0; }
    TFR(13) TFR(15) TFR(26) TFR(6)
    x0 += ks1; x1 += ks2 + 1u;
    TFR(17) TFR(29) TFR(16) TFR(24)
    x0 += ks2; x1 += ks0 + 2u;
    TFR(13) TFR(15) TFR(26) TFR(6)
    x0 += ks0; x1 += ks1 + 3u;
    TFR(17) TFR(29) TFR(16) TFR(24)
    x0 += ks1; x1 += ks2 + 4u;
    TFR(13) TFR(15) TFR(26) TFR(6)
    x0 += ks2; x1 += ks0 + 5u;
#undef TFR
    return make_uint2(x0, x1);
}

// ---------------- k0: fold avgpool(2x2,/4) into conv weights ----------------
// Wp[c][u][v][oc] = 0.25 * sum_{dh,dw in {0,1}, 0<=u-dh<5, 0<=v-dw<5} W[oc][c][u-dh][v-dw]
__global__ void k_fold(const float* __restrict__ Win, const float* __restrict__ Wh1) {
    int i = blockIdx.x * blockDim.x + threadIdx.x;
    if (i < 3*36*32) {
        int oc = i & 31; int r = i >> 5; int uv = r % 36; int c = r / 36;
        int u = uv / 6, v = uv % 6;
        float s = 0.f;
        #pragma unroll
        for (int dh = 0; dh < 2; dh++)
            #pragma unroll
            for (int dw = 0; dw < 2; dw++) {
                int kh = u - dh, kw = v - dw;
                if (kh >= 0 && kh < 5 && kw >= 0 && kw < 5)
                    s += Win[(oc*3 + c)*25 + kh*5 + kw];
            }
        g_Wp1[i] = 0.25f * s;
    }
    if (i < 32*36*64) {
        int oc = i & 63; int r = i >> 6; int uv = r % 36; int c = r / 36;
        int u = uv / 6, v = uv % 6;
        float s = 0.f;
        #pragma unroll
        for (int dh = 0; dh < 2; dh++)
            #pragma unroll
            for (int dw = 0; dw < 2; dw++) {
                int kh = u - dh, kw = v - dw;
                if (kh >= 0 && kh < 5 && kw >= 0 && kw < 5)
                    s += Wh1[(oc*32 + c)*25 + kh*5 + kw];
            }
        g_Wp2[i] = 0.25f * s;
    }
}

// ---------------- k1: poisson spike generation (JAX partitionable threefry) --
__global__ void k_spikes(const float* __restrict__ x) {
    int i = blockIdx.x * blockDim.x + threadIdx.x;
    if (i >= NSPK) return;
    uint2 r = threefry2x32(0u, 1u, 0u, (uint32_t)i);
    uint32_t bits = r.x ^ r.y;
    float u = __uint_as_float((bits >> 9) | 0x3f800000u) - 1.0f;
    int pos = i % XSZ;                     // [b][c][h][w] position
    g_spk0[i] = (u < x[pos] * 2.0f) ? 1 : 0;
}

// ---------------- k2: conv1(5x5) + avgpool fused via pooled 6x6 kernel ------
// one block per (t,b); thread = pooled spatial position, 32 oc accumulators
__global__ void k_conv1(void) {
    __shared__ float sIn[3*32*32];
    __shared__ __align__(16) float sW[3*36*32];
    int tb = blockIdx.x;
    const unsigned char* inp = g_spk0 + (size_t)tb * 3072;
    for (int i = threadIdx.x; i < 3072; i += blockDim.x) sIn[i] = (float)inp[i];
    for (int i = threadIdx.x; i < 3456; i += blockDim.x) sW[i] = g_Wp1[i];
    __syncthreads();

    int sp = threadIdx.x;
    if (sp >= 196) return;
    int ph = sp / 14, pw = sp % 14;
    float acc[32];
    #pragma unroll
    for (int j = 0; j < 32; j++) acc[j] = 0.f;

    int ibase = ph*64 + pw*2;              // (2ph)*32 + 2pw
    for (int c = 0; c < 3; c++) {
        const float* sI  = &sIn[c*1024 + ibase];
        const float* sWc = &sW[c*36*32];
        for (int u = 0; u < 6; u++) {
            #pragma unroll
            for (int v = 0; v < 6; v++) {
                float s = sI[u*32 + v];
                const float4* w4 = (const float4*)&sWc[(u*6 + v)*32];
                #pragma unroll
                for (int j = 0; j < 8; j++) {
                    float4 w = w4[j];
                    acc[4*j+0] += s * w.x;
                    acc[4*j+1] += s * w.y;
                    acc[4*j+2] += s * w.z;
                    acc[4*j+3] += s * w.w;
                }
            }
        }
    }
    size_t ob = (size_t)tb * (32*196);
    #pragma unroll 32
    for (int oc = 0; oc < 32; oc++) g_curin[ob + oc*196 + sp] = acc[oc];
}

// ---------------- k3: LIF scan layer 1 (mem[t]=cur[t]-spk[t-1]) ------------
__global__ void k_lif1(void) {
    int n = blockIdx.x * blockDim.x + threadIdx.x;
    if (n >= N1) return;
    float spk = 0.f;
    for (int t = 0; t < STEPS; t++) {
        float mem = g_curin[(size_t)t*N1 + n] - spk;
        spk = (mem > 1.0f) ? 1.0f : 0.0f;
        g_spkin[(size_t)t*N1 + n] = (unsigned char)(mem > 1.0f);
    }
}

// ---------------- k4: conv2 + pool, SPARSE over active input spikes --------
// block per (t,b). Deterministic per-channel active list; per-c weight slice
// staged in shared. Thread = (spatial pos, oc-octet): pure FADD gather.
__global__ void k_conv2(void) {
    __shared__ unsigned char sList[32*196];
    __shared__ int sCnt[32];
    __shared__ __align__(16) float sW[36*64];

    int tb  = blockIdx.x;
    int tid = threadIdx.x;
    const unsigned char* inp = g_spkin + (size_t)tb * 6272;

    // deterministic active-list build: one thread per input channel, fixed order
    if (tid < 32) {
        int c = tid, n = 0;
        const unsigned char* pc = inp + c*196;
        for (int ih = 0; ih < 14; ih++)
            for (int iw = 0; iw < 14; iw++)
                if (pc[ih*14 + iw]) sList[c*196 + (n++)] = (unsigned char)((ih << 4) | iw);
        sCnt[c] = n;
    }

    int active = (tid < 200);
    int sp = tid >> 3;            // pooled spatial 0..24 (for active threads)
    int og = tid & 7;             // oc octet: oc = og*8 .. og*8+7
    int ph = sp / 5, pw = sp % 5;
    int ph2 = 2*ph, pw2 = 2*pw;
    float acc[8];
    #pragma unroll
    for (int j = 0; j < 8; j++) acc[j] = 0.f;

    for (int c = 0; c < 32; c++) {
        for (int i = tid; i < 2304; i += 256) sW[i] = g_Wp2[c*2304 + i];
        __syncthreads();              // also orders sList build before first use
        if (active) {
            int n = sCnt[c];
            const unsigned char* lst = &sList[c*196];
            for (int j = 0; j < n; j++) {
                int p = lst[j];
                int u = (p >> 4) - ph2;
                int v = (p & 15) - pw2;
                if ((unsigned)u < 6u && (unsigned)v < 6u) {
                    const float* w = &sW[(u*6 + v)*64 + og*8];
                    float4 a = *(const float4*)w;
                    float4 b = *(const float4*)(w + 4);
                    acc[0] += a.x; acc[1] += a.y; acc[2] += a.z; acc[3] += a.w;
                    acc[4] += b.x; acc[5] += b.y; acc[6] += b.z; acc[7] += b.w;
                }
            }
        }
        __syncthreads();              // protect sW reload next iteration
    }

    if (active) {
        size_t ob = (size_t)tb * 1600;
        #pragma unroll
        for (int j = 0; j < 8; j++)
            g_curh1[ob + (og*8 + j)*25 + sp] = acc[j];
    }
}

// ---------------- k5: LIF scan layer 2 -------------------------------------
__global__ void k_lif2(void) {
    int n = blockIdx.x * blockDim.x + threadIdx.x;
    if (n >= N2) return;
    float spk = 0.f;
    for (int t = 0; t < STEPS; t++) {
        float mem = g_curh1[(size_t)t*N2 + n] - spk;
        spk = (mem > 1.0f) ? 1.0f : 0.0f;
        g_spkh1[(size_t)t*N2 + n] = (unsigned char)(mem > 1.0f);
    }
}

// ---------------- k6: FC [6400,1600] x [1600,10] ---------------------------
// block per (t,b), 10 warps (one per output), lane-strided reduction
__global__ void k_fc(const float* __restrict__ Wh2) {
    int tb = blockIdx.x;
    int o = threadIdx.x >> 5;
    int lane = threadIdx.x & 31;
    const unsigned char* s = g_spkh1 + (size_t)tb * 1600;
    const float* w = Wh2 + o*1600;
    float acc = 0.f;
    for (int f = lane; f < 1600; f += 32) acc += (float)s[f] * w[f];
    #pragma unroll
    for (int off = 16; off; off >>= 1) acc += __shfl_down_sync(0xffffffffu, acc, off);
    if (lane == 0) g_fc[tb*10 + o] = acc;
}

// ---------------- k7: output LIF scan + write spikes and mem ---------------
__global__ void k_lif3(float* __restrict__ out) {
    int i = blockIdx.x * blockDim.x + threadIdx.x;
    if (i >= BATCH*10) return;
    float spk = 0.f;
    for (int t = 0; t < STEPS; t++) {
        float mem = g_fc[t*640 + i] - spk;
        spk = (mem > 1.0f) ? 1.0f : 0.0f;
        out[t*640 + i] = spk;                    // out_spikes [100,64,10]
        out[STEPS*640 + t*640 + i] = mem;        // memh2      [100,64,10]
    }
}

// ---------------- launcher -------------------------------------------------
extern "C" void kernel_launch(void* const* d_in, const int* in_sizes, int n_in,
                              void* d_out, int out_size) {
    const float* x   = (const float*)d_in[0];   // [64,3,32,32]
    const float* Win = (const float*)d_in[1];   // [32,3,5,5]
    const float* Wh1 = (const float*)d_in[2];   // [64,32,5,5]
    const float* Wh2 = (const float*)d_in[3];   // [10,1600]
    float* out = (float*)d_out;

    k_fold  <<<288, 256>>>(Win, Wh1);
    k_spikes<<<(NSPK + 255)/256, 256>>>(x);
    k_conv1 <<<TB, 224>>>();
    k_lif1  <<<(N1 + 255)/256, 256>>>();
    k_conv2 <<<TB, 256>>>();
    k_lif2  <<<(N2 + 255)/256, 256>>>();
    k_fc    <<<TB, 320>>>(Wh2);
    k_lif3  <<<3, 256>>>(out);
}